// round 8
// baseline (speedup 1.0000x reference)
#include <cuda_runtime.h>
#include <cuda_bf16.h>

// Problem constants (from setup_inputs):
//   B=1, NC=6 cameras, C=256 channels, nq=900 queries, 4 FPN levels.
//   Level sizes (H,W): (116,200) (58,100) (29,50) (15,25)
// Output tuple flattened in order:
//   ref3d        [1,900,3]            -> out[0 : 2700)
//   sampled_feats[1,256,900,6,1,4]    -> out[2700 : 2700+5529600)
//   mask         [1,1,900,6,1,1]      -> out[2700+5529600 : +5400)
//
// Thread model: block = 192 threads = 8 queries x 6 cams x 4 levels.
//   Each thread owns one (query, cam, level): computes projection + bilinear
//   corner indices/weights in registers, then loops 32 channels (blockIdx.y
//   selects the channel chunk). Stores per channel are contiguous across the
//   block (tid maps exactly to the (q,n,l) minor dims of the output).
// Feature loads for out-of-frustum samples (all corners invalid) are skipped
// entirely; this is exact (reference multiplies those terms by valid=0 and
// all inputs are finite).

#define FS_EPS 1e-5f
#define NQ 900
#define NCAM 6
#define NCH 256
#define QPB 8              // queries per block
#define CPB 32             // channels per block (x-loop)
#define THREADS (QPB * NCAM * 4)   // 192

__global__ __launch_bounds__(THREADS)
void fs_sample_kernel(
    const float* __restrict__ f0,   // [6,256,116,200]
    const float* __restrict__ f1,   // [6,256, 58,100]
    const float* __restrict__ f2,   // [6,256, 29, 50]
    const float* __restrict__ f3,   // [6,256, 15, 25]
    const float* __restrict__ ref,  // [900,3]
    const float* __restrict__ pc,   // [6]
    const float* __restrict__ img,  // [2] = {H=928, W=1600}
    const float* __restrict__ l2i,  // [6,4,4]
    float* __restrict__ out)
{
    const int t    = threadIdx.x;        // 0..191
    const int pair = t >> 2;             // 0..47  (= qsub*6 + n)
    const int l    = t & 3;              // level
    const int qsub = pair / NCAM;
    const int n    = pair - qsub * NCAM;
    const int q    = blockIdx.x * QPB + qsub;
    const int cbase = blockIdx.y * CPB;

    float* sampled = out + NQ * 3;                       // 2700
    float* maskout = out + NQ * 3 + NCH * NQ * NCAM * 4; // 2700 + 5529600

    // ref3d passthrough (only channel-chunk 0 blocks)
    if (blockIdx.y == 0 && t < QPB * 3) {
        int qq = blockIdx.x * QPB + t / 3;
        if (qq < NQ) out[qq * 3 + (t % 3)] = ref[qq * 3 + (t % 3)];
    }

    const bool active = (q < NQ);

    int   idx[4] = {-1, -1, -1, -1};
    float w[4]   = {0.f, 0.f, 0.f, 0.f};
    int   HW = 1;
    const float* featb = f0;

    if (active) {
        // --- projection (matches reference arithmetic order) ---
        const float rx = ref[q * 3 + 0];
        const float ry = ref[q * 3 + 1];
        const float rz = ref[q * 3 + 2];
        const float px = rx * (pc[3] - pc[0]) + pc[0];
        const float py = ry * (pc[4] - pc[1]) + pc[1];
        const float pz = rz * (pc[5] - pc[2]) + pc[2];
        const float* M = l2i + n * 16;
        const float c0 = M[0] * px + M[1] * py + M[2]  * pz + M[3];
        const float c1 = M[4] * px + M[5] * py + M[6]  * pz + M[7];
        const float c2 = M[8] * px + M[9] * py + M[10] * pz + M[11];
        const float zd = fmaxf(c2, FS_EPS);
        const float gx = (c0 / zd / img[1] - 0.5f) * 2.0f;
        const float gy = (c1 / zd / img[0] - 0.5f) * 2.0f;

        if (l == 0 && blockIdx.y == 0) {
            const bool m = (c2 > FS_EPS) &&
                           (gx > -1.0f) && (gx < 1.0f) &&
                           (gy > -1.0f) && (gy < 1.0f);
            maskout[q * NCAM + n] = m ? 1.0f : 0.0f;
        }

        // --- per-level bilinear setup ---
        const int Ws[4] = {200, 100, 50, 25};
        const int Hs[4] = {116,  58, 29, 15};
        const int Wl = Ws[l];
        const int Hl = Hs[l];
        HW = Wl * Hl;
        featb = (l == 0) ? f0 : (l == 1) ? f1 : (l == 2) ? f2 : f3;

        const float ix  = ((gx + 1.0f) * (float)Wl - 1.0f) * 0.5f;
        const float iy  = ((gy + 1.0f) * (float)Hl - 1.0f) * 0.5f;
        const float ix0 = floorf(ix);
        const float iy0 = floorf(iy);
        const float wx1 = ix - ix0;
        const float wy1 = iy - iy0;
        const float wx0 = 1.0f - wx1;
        const float wy0 = 1.0f - wy1;

        const bool vx0 = (ix0        >= 0.0f) && (ix0        <= (float)(Wl - 1));
        const bool vx1 = (ix0 + 1.0f >= 0.0f) && (ix0 + 1.0f <= (float)(Wl - 1));
        const bool vy0 = (iy0        >= 0.0f) && (iy0        <= (float)(Hl - 1));
        const bool vy1 = (iy0 + 1.0f >= 0.0f) && (iy0 + 1.0f <= (float)(Hl - 1));

        // int conversion only meaningful when some corner is valid (then in range)
        const int ixi = (int)ix0;
        const int iyi = (int)iy0;
        if (vy0 && vx0) { idx[0] =  iyi      * Wl + ixi;     w[0] = wy0 * wx0; }
        if (vy0 && vx1) { idx[1] =  iyi      * Wl + ixi + 1; w[1] = wy0 * wx1; }
        if (vy1 && vx0) { idx[2] = (iyi + 1) * Wl + ixi;     w[2] = wy1 * wx0; }
        if (vy1 && vx1) { idx[3] = (iyi + 1) * Wl + ixi + 1; w[3] = wy1 * wx1; }
    }

    // --- channel gather loop ---
    // feat element: featb[ (n*256 + c) * HW + idx ]
    // out element : sampled[ ((c*900 + q)*6 + n)*4 + l ]
    const float* p = featb + (size_t)(n * NCH + cbase) * (size_t)HW;
    float* op = sampled + ((size_t)cbase * NQ + q) * (NCAM * 4) + n * 4 + l;
    const bool anyload = active && ((idx[0] | idx[1] | idx[2] | idx[3]) >= 0 ||
                                    idx[0] >= 0 || idx[1] >= 0 || idx[2] >= 0 || idx[3] >= 0);

    #pragma unroll 4
    for (int cc = 0; cc < CPB; cc++) {
        float acc = 0.0f;
        if (anyload) {
            if (idx[0] >= 0) acc += w[0] * __ldg(p + idx[0]);
            if (idx[1] >= 0) acc += w[1] * __ldg(p + idx[1]);
            if (idx[2] >= 0) acc += w[2] * __ldg(p + idx[2]);
            if (idx[3] >= 0) acc += w[3] * __ldg(p + idx[3]);
        }
        if (active) *op = acc;
        p  += HW;
        op += NQ * NCAM * 4;   // 21600 floats per channel step
    }
}

extern "C" void kernel_launch(void* const* d_in, const int* in_sizes, int n_in,
                              void* d_out, int out_size) {
    const float* f0  = (const float*)d_in[0];
    const float* f1  = (const float*)d_in[1];
    const float* f2  = (const float*)d_in[2];
    const float* f3  = (const float*)d_in[3];
    const float* ref = (const float*)d_in[4];
    const float* pc  = (const float*)d_in[5];
    const float* img = (const float*)d_in[6];
    const float* l2i = (const float*)d_in[7];
    float* out = (float*)d_out;

    dim3 grid((NQ + QPB - 1) / QPB, NCH / CPB);  // (113, 8)
    fs_sample_kernel<<<grid, THREADS>>>(f0, f1, f2, f3, ref, pc, img, l2i, out);
}

// round 9
// speedup vs baseline: 1.0094x; 1.0094x over previous
#include <cuda_runtime.h>
#include <cuda_bf16.h>

// Problem constants (from setup_inputs):
//   B=1, NC=6 cameras, C=256 channels, nq=900 queries, 4 FPN levels.
//   Level sizes (H,W): (116,200) (58,100) (29,50) (15,25)
// Output tuple flattened in order:
//   ref3d        [1,900,3]            -> out[0 : 2700)
//   sampled_feats[1,256,900,6,1,4]    -> out[2700 : 2700+5529600)
//   mask         [1,1,900,6,1,1]      -> out[2700+5529600 : +5400)
//
// Thread model: block = 192 threads = 8 queries x 6 cams x 4 levels.
// Each thread owns one (query, cam, level). Projection + bilinear setup is
// hoisted entirely out of the channel loop: corner indices are CLAMPED into
// range and invalid corners get weight 0 (exact — reference multiplies those
// terms by valid=0; clamped loads are legal memory). One `anyvalid` predicate
// gates the loads; fully-out-of-frustum threads (~87%) issue no loads and
// only the (coalesced, mandatory) zero stores.
// __launch_bounds__(192,7) caps regs at 48 -> 42 warps/SM and 7 blocks/SM
// resident, so the whole 904-block grid runs in ONE wave.

#define FS_EPS 1e-5f
#define NQ 900
#define NCAM 6
#define NCH 256
#define QPB 8              // queries per block
#define CPB 32             // channels per block (grid.y chunk)
#define THREADS (QPB * NCAM * 4)   // 192

__global__ __launch_bounds__(THREADS, 7)
void fs_sample_kernel(
    const float* __restrict__ f0,   // [6,256,116,200]
    const float* __restrict__ f1,   // [6,256, 58,100]
    const float* __restrict__ f2,   // [6,256, 29, 50]
    const float* __restrict__ f3,   // [6,256, 15, 25]
    const float* __restrict__ ref,  // [900,3]
    const float* __restrict__ pc,   // [6]
    const float* __restrict__ img,  // [2] = {H=928, W=1600}
    const float* __restrict__ l2i,  // [6,4,4]
    float* __restrict__ out)
{
    const int t    = threadIdx.x;        // 0..191
    const int pair = t >> 2;             // 0..47  (= qsub*6 + n)
    const int l    = t & 3;              // level
    const int qsub = pair / NCAM;
    const int n    = pair - qsub * NCAM;
    const int q    = blockIdx.x * QPB + qsub;
    const int cbase = blockIdx.y * CPB;

    float* sampled = out + NQ * 3;                       // 2700
    float* maskout = out + NQ * 3 + NCH * NQ * NCAM * 4; // 2700 + 5529600

    // ref3d passthrough (only channel-chunk 0 blocks)
    if (blockIdx.y == 0 && t < QPB * 3) {
        int qq = blockIdx.x * QPB + t / 3;
        if (qq < NQ) out[qq * 3 + (t % 3)] = ref[qq * 3 + (t % 3)];
    }

    const bool active = (q < NQ);

    int   i00 = 0, i01 = 0, i10 = 0, i11 = 0;
    float w00 = 0.f, w01 = 0.f, w10 = 0.f, w11 = 0.f;
    bool  anyvalid = false;
    int   HW = 1;
    const float* featb = f0;

    if (active) {
        // --- projection (matches reference arithmetic order) ---
        const float rx = ref[q * 3 + 0];
        const float ry = ref[q * 3 + 1];
        const float rz = ref[q * 3 + 2];
        const float px = rx * (pc[3] - pc[0]) + pc[0];
        const float py = ry * (pc[4] - pc[1]) + pc[1];
        const float pz = rz * (pc[5] - pc[2]) + pc[2];
        const float* M = l2i + n * 16;
        const float c0 = M[0] * px + M[1] * py + M[2]  * pz + M[3];
        const float c1 = M[4] * px + M[5] * py + M[6]  * pz + M[7];
        const float c2 = M[8] * px + M[9] * py + M[10] * pz + M[11];
        const float zd = fmaxf(c2, FS_EPS);
        const float gx = (c0 / zd / img[1] - 0.5f) * 2.0f;
        const float gy = (c1 / zd / img[0] - 0.5f) * 2.0f;

        if (l == 0 && blockIdx.y == 0) {
            const bool m = (c2 > FS_EPS) &&
                           (gx > -1.0f) && (gx < 1.0f) &&
                           (gy > -1.0f) && (gy < 1.0f);
            maskout[q * NCAM + n] = m ? 1.0f : 0.0f;
        }

        // --- per-level bilinear setup ---
        const int Ws[4] = {200, 100, 50, 25};
        const int Hs[4] = {116,  58, 29, 15};
        const int Wl = Ws[l];
        const int Hl = Hs[l];
        HW = Wl * Hl;
        featb = (l == 0) ? f0 : (l == 1) ? f1 : (l == 2) ? f2 : f3;

        const float ix  = ((gx + 1.0f) * (float)Wl - 1.0f) * 0.5f;
        const float iy  = ((gy + 1.0f) * (float)Hl - 1.0f) * 0.5f;
        const float ix0 = floorf(ix);
        const float iy0 = floorf(iy);
        const float wx1 = ix - ix0;
        const float wy1 = iy - iy0;
        const float wx0 = 1.0f - wx1;
        const float wy0 = 1.0f - wy1;

        // side validity (NaN/Inf comparisons are false -> anyvalid false)
        const bool vx0 = (ix0        >= 0.0f) && (ix0        <= (float)(Wl - 1));
        const bool vx1 = (ix0 + 1.0f >= 0.0f) && (ix0 + 1.0f <= (float)(Wl - 1));
        const bool vy0 = (iy0        >= 0.0f) && (iy0        <= (float)(Hl - 1));
        const bool vy1 = (iy0 + 1.0f >= 0.0f) && (iy0 + 1.0f <= (float)(Hl - 1));
        anyvalid = (vx0 | vx1) & (vy0 | vy1);

        if (anyvalid) {
            // safe conversion: anyvalid implies ix0 in [-1, Wl-1], iy0 in [-1, Hl-1]
            const int ixi = (int)ix0;
            const int iyi = (int)iy0;
            const int xc0 = max(ixi,     0);            // clamp into range
            const int xc1 = min(ixi + 1, Wl - 1);
            const int yr0 = max(iyi,     0) * Wl;
            const int yr1 = min(iyi + 1, Hl - 1) * Wl;
            i00 = yr0 + xc0;  i01 = yr0 + xc1;
            i10 = yr1 + xc0;  i11 = yr1 + xc1;
            // zero weights of invalid corners (exact: reference uses w*valid)
            w00 = (vy0 && vx0) ? wy0 * wx0 : 0.f;
            w01 = (vy0 && vx1) ? wy0 * wx1 : 0.f;
            w10 = (vy1 && vx0) ? wy1 * wx0 : 0.f;
            w11 = (vy1 && vx1) ? wy1 * wx1 : 0.f;
        }
    }

    // --- channel gather loop (branch-free body) ---
    // feat element: featb[ (n*256 + c) * HW + idx ]
    // out element : sampled[ ((c*900 + q)*6 + n)*4 + l ]
    const float* p = featb + (size_t)(n * NCH + cbase) * (size_t)HW;
    float* op = sampled + ((size_t)cbase * NQ + q) * (NCAM * 4) + n * 4 + l;
    const bool doload = active && anyvalid;

    #pragma unroll
    for (int cc = 0; cc < CPB; cc++) {
        float acc = 0.0f;
        if (doload) {
            const float a = __ldg(p + i00);
            const float b = __ldg(p + i01);
            const float c = __ldg(p + i10);
            const float d = __ldg(p + i11);
            acc = fmaf(w00, a, fmaf(w01, b, fmaf(w10, c, w11 * d)));
        }
        if (active) *op = acc;
        p  += HW;
        op += NQ * NCAM * 4;   // 21600 floats per channel step
    }
}

extern "C" void kernel_launch(void* const* d_in, const int* in_sizes, int n_in,
                              void* d_out, int out_size) {
    const float* f0  = (const float*)d_in[0];
    const float* f1  = (const float*)d_in[1];
    const float* f2  = (const float*)d_in[2];
    const float* f3  = (const float*)d_in[3];
    const float* ref = (const float*)d_in[4];
    const float* pc  = (const float*)d_in[5];
    const float* img = (const float*)d_in[6];
    const float* l2i = (const float*)d_in[7];
    float* out = (float*)d_out;

    dim3 grid((NQ + QPB - 1) / QPB, NCH / CPB);  // (113, 8)
    fs_sample_kernel<<<grid, THREADS>>>(f0, f1, f2, f3, ref, pc, img, l2i, out);
}

// round 11
// speedup vs baseline: 1.2892x; 1.2771x over previous
#include <cuda_runtime.h>
#include <cuda_bf16.h>

// DETR3D feature sampling. B=1, NC=6 cams, C=256, nq=900, 4 FPN levels
// (H,W): (116,200) (58,100) (29,50) (15,25).
// Output: ref3d[900,3] | sampled[256,900,6,1,4] | mask[900,6].
//
// Thread model (corner-pair lane sharing):
//   block = 192 threads = 8 queries x 6 cams x (2 levels-halves x 2 xsides).
//   s = t>>2 selects (query,cam); xside = t&1 selects the x column
//   (xc0 or xc1); lhalf = (t>>1)&1 selects level set {lhalf, lhalf+2}.
//   Lanes (t, t^1) form a pair working on the SAME sample: their column
//   indices differ by 1, so the row0 loads of both lanes sit in the same
//   LDG instruction and the same 128B line -> ONE L1 wavefront (likewise
//   row1). This halves gather wavefronts vs one-lane-per-sample (4 -> 2
//   per valid sample-channel), attacking the measured L1=64% ceiling.
//   The bilinear sum is completed with one __shfl_xor(+) across the pair.
// Out-of-frustum samples (~87%) skip loads entirely (exact: reference
// multiplies those corners by valid=0). Corner indices are clamped and
// invalid corner weights zeroed, so the loop body is branch-free.

#define FS_EPS 1e-5f
#define NQ 900
#define NCAM 6
#define NCH 256
#define QPB 8              // queries per block
#define CPB 32             // channels per chunk (grid.y)
#define THREADS (QPB * NCAM * 4)   // 192

__global__ __launch_bounds__(THREADS, 8)
void fs_sample_kernel(
    const float* __restrict__ f0,   // [6,256,116,200]
    const float* __restrict__ f1,   // [6,256, 58,100]
    const float* __restrict__ f2,   // [6,256, 29, 50]
    const float* __restrict__ f3,   // [6,256, 15, 25]
    const float* __restrict__ ref,  // [900,3]
    const float* __restrict__ pc,   // [6]
    const float* __restrict__ img,  // [2] = {H=928, W=1600}
    const float* __restrict__ l2i,  // [6,4,4]
    float* __restrict__ out)
{
    const int t     = threadIdx.x;       // 0..191
    const int xside = t & 1;             // which x column of the bilinear pair
    const int lhalf = (t >> 1) & 1;      // levels {lhalf, lhalf+2}
    const int s     = t >> 2;            // 0..47 = qsub*6 + n
    const int qsub  = s / NCAM;
    const int n     = s - qsub * NCAM;
    const int q     = blockIdx.x * QPB + qsub;
    const int cbase = blockIdx.y * CPB;

    float* sampled = out + NQ * 3;                       // 2700
    float* maskout = out + NQ * 3 + NCH * NQ * NCAM * 4; // 2700 + 5529600

    // ref3d passthrough (channel-chunk 0 blocks only)
    if (blockIdx.y == 0 && t < QPB * 3) {
        int qq = blockIdx.x * QPB + t / 3;
        if (qq < NQ) out[qq * 3 + (t % 3)] = ref[qq * 3 + (t % 3)];
    }

    const bool active = (q < NQ);

    // --- projection (level-independent, matches reference arithmetic) ---
    float gx = 0.f, gy = 0.f;
    if (active) {
        const float rx = ref[q * 3 + 0];
        const float ry = ref[q * 3 + 1];
        const float rz = ref[q * 3 + 2];
        const float px = rx * (pc[3] - pc[0]) + pc[0];
        const float py = ry * (pc[4] - pc[1]) + pc[1];
        const float pz = rz * (pc[5] - pc[2]) + pc[2];
        const float* M = l2i + n * 16;
        const float c0 = M[0] * px + M[1] * py + M[2]  * pz + M[3];
        const float c1 = M[4] * px + M[5] * py + M[6]  * pz + M[7];
        const float c2 = M[8] * px + M[9] * py + M[10] * pz + M[11];
        const float zd = fmaxf(c2, FS_EPS);
        gx = (c0 / zd / img[1] - 0.5f) * 2.0f;
        gy = (c1 / zd / img[0] - 0.5f) * 2.0f;

        if ((t & 3) == 0 && blockIdx.y == 0) {
            const bool m = (c2 > FS_EPS) &&
                           (gx > -1.0f) && (gx < 1.0f) &&
                           (gy > -1.0f) && (gy < 1.0f);
            maskout[q * NCAM + n] = m ? 1.0f : 0.0f;
        }
    }

    #pragma unroll
    for (int lv = 0; lv < 2; lv++) {
        const int l = lhalf + 2 * lv;        // this thread's level

        const int   Wl = (l == 0) ? 200 : (l == 1) ? 100 : (l == 2) ? 50 : 25;
        const int   Hl = (l == 0) ? 116 : (l == 1) ?  58 : (l == 2) ? 29 : 15;
        const int   HW = Wl * Hl;
        const float* featb = (l == 0) ? f0 : (l == 1) ? f1 : (l == 2) ? f2 : f3;

        int   j0 = 0, j1 = 0;
        float w0 = 0.f, w1 = 0.f;
        bool  doload = false;

        if (active) {
            const float ix  = ((gx + 1.0f) * (float)Wl - 1.0f) * 0.5f;
            const float iy  = ((gy + 1.0f) * (float)Hl - 1.0f) * 0.5f;
            const float ix0 = floorf(ix);
            const float iy0 = floorf(iy);
            const float wx1 = ix - ix0;
            const float wy1 = iy - iy0;
            const float wx0 = 1.0f - wx1;
            const float wy0 = 1.0f - wy1;

            // side validity (NaN comparisons are false -> anyvalid false)
            const bool vx0 = (ix0        >= 0.0f) && (ix0        <= (float)(Wl - 1));
            const bool vx1 = (ix0 + 1.0f >= 0.0f) && (ix0 + 1.0f <= (float)(Wl - 1));
            const bool vy0 = (iy0        >= 0.0f) && (iy0        <= (float)(Hl - 1));
            const bool vy1 = (iy0 + 1.0f >= 0.0f) && (iy0 + 1.0f <= (float)(Hl - 1));
            const bool anyvalid = (vx0 | vx1) & (vy0 | vy1);  // identical for both pair lanes

            if (anyvalid) {
                // anyvalid implies ix0 in [-1, Wl-1], iy0 in [-1, Hl-1] -> safe int conv
                const int ixi = (int)ix0;
                const int iyi = (int)iy0;
                const int xc0 = max(ixi,     0);
                const int xc1 = min(ixi + 1, Wl - 1);
                const int yr0 = max(iyi,     0) * Wl;
                const int yr1 = min(iyi + 1, Hl - 1) * Wl;

                const int   xs  = xside ? xc1 : xc0;   // this lane's column (clamped)
                const bool  vxs = xside ? vx1 : vx0;
                const float wxs = xside ? wx1 : wx0;
                j0 = yr0 + xs;
                j1 = yr1 + xs;
                w0 = (vy0 && vxs) ? wy0 * wxs : 0.f;   // zero invalid corners (exact)
                w1 = (vy1 && vxs) ? wy1 * wxs : 0.f;
                doload = true;                          // uniform across the pair
            }
        }

        // --- channel loop ---
        // feat element: featb[(n*256 + c)*HW + j]
        // out element : sampled[((c*900 + q)*6 + n)*4 + l]
        const float* p  = featb + (size_t)(n * NCH + cbase) * (size_t)HW;
        float*       op = sampled + ((size_t)cbase * NQ + q) * (NCAM * 4) + n * 4 + l;
        const bool   dostore = active && (xside == 0);

        #pragma unroll
        for (int cc = 0; cc < CPB; cc++) {
            float acc = 0.0f;
            if (doload) {
                // pair lanes' j0 differ by 1 -> same line, one wavefront per LDG
                acc = fmaf(w0, __ldg(p + j0), w1 * __ldg(p + j1));
            }
            // complete bilinear sum across the (xc0, xc1) lane pair
            const float sum = acc + __shfl_xor_sync(0xffffffffu, acc, 1);
            if (dostore) *op = sum;
            p  += HW;
            op += NQ * NCAM * 4;   // 21600 floats per channel step
        }
    }
}

extern "C" void kernel_launch(void* const* d_in, const int* in_sizes, int n_in,
                              void* d_out, int out_size) {
    const float* f0  = (const float*)d_in[0];
    const float* f1  = (const float*)d_in[1];
    const float* f2  = (const float*)d_in[2];
    const float* f3  = (const float*)d_in[3];
    const float* ref = (const float*)d_in[4];
    const float* pc  = (const float*)d_in[5];
    const float* img = (const float*)d_in[6];
    const float* l2i = (const float*)d_in[7];
    float* out = (float*)d_out;

    dim3 grid((NQ + QPB - 1) / QPB, NCH / CPB);  // (113, 8)
    fs_sample_kernel<<<grid, THREADS>>>(f0, f1, f2, f3, ref, pc, img, l2i, out);
}

// round 12
// speedup vs baseline: 1.3049x; 1.0122x over previous
#include <cuda_runtime.h>
#include <cuda_bf16.h>

// DETR3D feature sampling. B=1, NC=6 cams, C=256, nq=900, 4 FPN levels
// (H,W): (116,200) (58,100) (29,50) (15,25).
// Output: ref3d[900,3] | sampled[256,900,6,1,4] | mask[900,6].
//
// Thread model (corner-pair lane sharing):
//   block = 192 threads = 8 queries x 6 cams x (2 level-halves x 2 xsides).
//   Lanes (t, t^1) work on the SAME sample; each owns one x column of the
//   bilinear quad, so the row0 loads of both lanes coalesce into ONE L1
//   wavefront (likewise row1): 2 wavefronts per valid sample-channel
//   instead of 4. The bilinear sum completes with one __shfl_xor(+).
// Out-of-frustum samples (~87%) skip loads entirely (exact: reference
// multiplies those corners by valid=0). Corner indices clamped, invalid
// corner weights zeroed -> branch-free channel loop.
//
// R11 change: CPB 32 -> 16 doubles the grid to 1808 blocks (12.2/SM) so the
// 8-block/SM residency cap (48 warps, 75%) is actually reached; previously
// only 904 blocks existed (6.1/SM, ~36 warps) and the kernel was
// latency-bound with idle schedulers (issue=25%).

#define FS_EPS 1e-5f
#define NQ 900
#define NCAM 6
#define NCH 256
#define QPB 8              // queries per block
#define CPB 16             // channels per chunk (grid.y)
#define THREADS (QPB * NCAM * 4)   // 192

__global__ __launch_bounds__(THREADS, 8)
void fs_sample_kernel(
    const float* __restrict__ f0,   // [6,256,116,200]
    const float* __restrict__ f1,   // [6,256, 58,100]
    const float* __restrict__ f2,   // [6,256, 29, 50]
    const float* __restrict__ f3,   // [6,256, 15, 25]
    const float* __restrict__ ref,  // [900,3]
    const float* __restrict__ pc,   // [6]
    const float* __restrict__ img,  // [2] = {H=928, W=1600}
    const float* __restrict__ l2i,  // [6,4,4]
    float* __restrict__ out)
{
    const int t     = threadIdx.x;       // 0..191
    const int xside = t & 1;             // which x column of the bilinear pair
    const int lhalf = (t >> 1) & 1;      // levels {lhalf, lhalf+2}
    const int s     = t >> 2;            // 0..47 = qsub*6 + n
    const int qsub  = s / NCAM;
    const int n     = s - qsub * NCAM;
    const int q     = blockIdx.x * QPB + qsub;
    const int cbase = blockIdx.y * CPB;

    float* sampled = out + NQ * 3;                       // 2700
    float* maskout = out + NQ * 3 + NCH * NQ * NCAM * 4; // 2700 + 5529600

    // ref3d passthrough (channel-chunk 0 blocks only)
    if (blockIdx.y == 0 && t < QPB * 3) {
        int qq = blockIdx.x * QPB + t / 3;
        if (qq < NQ) out[qq * 3 + (t % 3)] = ref[qq * 3 + (t % 3)];
    }

    const bool active = (q < NQ);

    // --- projection (level-independent, matches reference arithmetic) ---
    float gx = 0.f, gy = 0.f;
    if (active) {
        const float rx = ref[q * 3 + 0];
        const float ry = ref[q * 3 + 1];
        const float rz = ref[q * 3 + 2];
        const float px = rx * (pc[3] - pc[0]) + pc[0];
        const float py = ry * (pc[4] - pc[1]) + pc[1];
        const float pz = rz * (pc[5] - pc[2]) + pc[2];
        const float* M = l2i + n * 16;
        const float c0 = M[0] * px + M[1] * py + M[2]  * pz + M[3];
        const float c1 = M[4] * px + M[5] * py + M[6]  * pz + M[7];
        const float c2 = M[8] * px + M[9] * py + M[10] * pz + M[11];
        const float zd = fmaxf(c2, FS_EPS);
        gx = (c0 / zd / img[1] - 0.5f) * 2.0f;
        gy = (c1 / zd / img[0] - 0.5f) * 2.0f;

        if ((t & 3) == 0 && blockIdx.y == 0) {
            const bool m = (c2 > FS_EPS) &&
                           (gx > -1.0f) && (gx < 1.0f) &&
                           (gy > -1.0f) && (gy < 1.0f);
            maskout[q * NCAM + n] = m ? 1.0f : 0.0f;
        }
    }

    #pragma unroll
    for (int lv = 0; lv < 2; lv++) {
        const int l = lhalf + 2 * lv;        // this thread's level

        const int   Wl = (l == 0) ? 200 : (l == 1) ? 100 : (l == 2) ? 50 : 25;
        const int   Hl = (l == 0) ? 116 : (l == 1) ?  58 : (l == 2) ? 29 : 15;
        const int   HW = Wl * Hl;
        const float* featb = (l == 0) ? f0 : (l == 1) ? f1 : (l == 2) ? f2 : f3;

        int   j0 = 0, j1 = 0;
        float w0 = 0.f, w1 = 0.f;
        bool  doload = false;

        if (active) {
            const float ix  = ((gx + 1.0f) * (float)Wl - 1.0f) * 0.5f;
            const float iy  = ((gy + 1.0f) * (float)Hl - 1.0f) * 0.5f;
            const float ix0 = floorf(ix);
            const float iy0 = floorf(iy);
            const float wx1 = ix - ix0;
            const float wy1 = iy - iy0;
            const float wx0 = 1.0f - wx1;
            const float wy0 = 1.0f - wy1;

            // side validity (NaN comparisons are false -> anyvalid false)
            const bool vx0 = (ix0        >= 0.0f) && (ix0        <= (float)(Wl - 1));
            const bool vx1 = (ix0 + 1.0f >= 0.0f) && (ix0 + 1.0f <= (float)(Wl - 1));
            const bool vy0 = (iy0        >= 0.0f) && (iy0        <= (float)(Hl - 1));
            const bool vy1 = (iy0 + 1.0f >= 0.0f) && (iy0 + 1.0f <= (float)(Hl - 1));
            const bool anyvalid = (vx0 | vx1) & (vy0 | vy1);  // identical for both pair lanes

            if (anyvalid) {
                // anyvalid implies ix0 in [-1, Wl-1], iy0 in [-1, Hl-1] -> safe int conv
                const int ixi = (int)ix0;
                const int iyi = (int)iy0;
                const int xc0 = max(ixi,     0);
                const int xc1 = min(ixi + 1, Wl - 1);
                const int yr0 = max(iyi,     0) * Wl;
                const int yr1 = min(iyi + 1, Hl - 1) * Wl;

                const int   xs  = xside ? xc1 : xc0;   // this lane's column (clamped)
                const bool  vxs = xside ? vx1 : vx0;
                const float wxs = xside ? wx1 : wx0;
                j0 = yr0 + xs;
                j1 = yr1 + xs;
                w0 = (vy0 && vxs) ? wy0 * wxs : 0.f;   // zero invalid corners (exact)
                w1 = (vy1 && vxs) ? wy1 * wxs : 0.f;
                doload = true;                          // uniform across the pair
            }
        }

        // --- channel loop ---
        // feat element: featb[(n*256 + c)*HW + j]
        // out element : sampled[((c*900 + q)*6 + n)*4 + l]
        const float* p  = featb + (size_t)(n * NCH + cbase) * (size_t)HW;
        float*       op = sampled + ((size_t)cbase * NQ + q) * (NCAM * 4) + n * 4 + l;
        const bool   dostore = active && (xside == 0);

        #pragma unroll
        for (int cc = 0; cc < CPB; cc++) {
            float acc = 0.0f;
            if (doload) {
                // pair lanes' j differ by 1 -> same line, one wavefront per LDG
                acc = fmaf(w0, __ldg(p + j0), w1 * __ldg(p + j1));
            }
            // complete bilinear sum across the (xc0, xc1) lane pair
            const float sum = acc + __shfl_xor_sync(0xffffffffu, acc, 1);
            if (dostore) *op = sum;
            p  += HW;
            op += NQ * NCAM * 4;   // 21600 floats per channel step
        }
    }
}

extern "C" void kernel_launch(void* const* d_in, const int* in_sizes, int n_in,
                              void* d_out, int out_size) {
    const float* f0  = (const float*)d_in[0];
    const float* f1  = (const float*)d_in[1];
    const float* f2  = (const float*)d_in[2];
    const float* f3  = (const float*)d_in[3];
    const float* ref = (const float*)d_in[4];
    const float* pc  = (const float*)d_in[5];
    const float* img = (const float*)d_in[6];
    const float* l2i = (const float*)d_in[7];
    float* out = (float*)d_out;

    dim3 grid((NQ + QPB - 1) / QPB, NCH / CPB);  // (113, 16) = 1808 blocks
    fs_sample_kernel<<<grid, THREADS>>>(f0, f1, f2, f3, ref, pc, img, l2i, out);
}